// round 10
// baseline (speedup 1.0000x reference)
#include <cuda_runtime.h>
#include <math.h>
#include <stdint.h>

#define Bsz 256
#define Ssz 2048
#define Dsz 64
#define Hsz 256
#define NCTA 128          // persistent CTAs, 1/SM, all co-resident
#define NTHR 512          // 16 warps: 12 compute, 4 util

// ---------------- device scratch ----------------
__device__ float g_pre0p[(size_t)NCTA * Ssz * 512];  // private pre0 [cta][s][row16][lane32]
__device__ float g_h0[2][Bsz * Hsz];                 // layer-0 state, double buffered
__device__ float g_h1[2][Bsz * Hsz];                 // layer-1 state, double buffered
__device__ unsigned int g_flags[NCTA];               // barrier flags (zeroed by init)

__device__ __forceinline__ float tanh_fast(float x) {
    float y; asm("tanh.approx.f32 %0, %1;" : "=f"(y) : "f"(x)); return y;
}
__device__ __forceinline__ unsigned long long fma2(unsigned long long a,
                                                   unsigned long long b,
                                                   unsigned long long c) {
    unsigned long long d;
    asm("fma.rn.f32x2 %0, %1, %2, %3;" : "=l"(d) : "l"(a), "l"(b), "l"(c));
    return d;
}

// ---------------- init: zero flags + seed states ----------------
__global__ void init_kernel() {
    const int idx = blockIdx.x * blockDim.x + threadIdx.x;
    if (idx < NCTA) g_flags[idx] = 0u;
    if (idx < Bsz * Hsz) {
        g_h0[1][idx] = 0.0f;
        g_h1[1][idx] = 0.0f;
        g_h1[0][idx] = 0.0f;
    }
}

__global__ void __launch_bounds__(NTHR, 1)
fused_kernel(const float* __restrict__ x,
             const float* __restrict__ Wih0,
             const float* __restrict__ Whh0,
             const float* __restrict__ bih0,
             const float* __restrict__ bhh0,
             const float* __restrict__ Wih1,
             const float* __restrict__ Whh1,
             const float* __restrict__ bih1,
             const float* __restrict__ bhh1,
             const float* __restrict__ Wout,
             const float* __restrict__ bout,
             float* __restrict__ out) {
    extern __shared__ float smem[];
    // weights, transposed: [k][col32]  (LDS.128 = 4 consecutive cols, conflict-free)
    float* sW0  = smem;                       // Whh0 : 256*32 = 8192 f
    float* sWi1 = sW0  + 8192;                // Wih1
    float* sWh1 = sWi1 + 8192;                // Whh1
    // states, transposed + duplicated: [k][2*row16]  (LDS.128 = 2 rows, fma2-ready)
    float* sH0T = sWh1 + 8192;                // 256*32 = 8192 f
    float* sH1T = sH0T + 8192;
    float* sRed = sH1T + 8192;                // 12 tiles of [16][34]

    const int tid  = threadIdx.x;
    const int cta  = blockIdx.x;
    const int grp8 = (cta >> 3) * 8;
    const int b0   = (cta >> 3) * 16;          // 16 batch rows
    const int h0c  = (cta & 7) * 32;           // 32 h columns
    const int lane = tid & 31;
    const int warp = tid >> 5;                 // 0..15
    // compute warps 0..11: 0-3 -> Whh0 k-quarter; 4-11 -> Wih1+Whh1 k-eighth
    const int uw   = warp - 12;                // util warps 12..15
    // lane tile: 4 rows x 4 cols
    const int rq = lane >> 3, cq = lane & 7;
    const int r0 = rq * 4, c0 = cq * 4;

    // ================= phase 1: pre0_priv = x @ Wih0^T + (b_ih0+b_hh0) =================
    {
        float* sW = sH0T;   // scratch region, overwritten later
        for (int it = tid; it < 32 * 16; it += NTHR) {
            const int col = it >> 4, kq = it & 15;
            *(float4*)(sW + (kq * 32 + col) * 4) =
                *(const float4*)(Wih0 + (size_t)(h0c + col) * Dsz + kq * 4);
        }
        __syncthreads();
        const float bsum = bih0[h0c + lane] + bhh0[h0c + lane];

        for (int s = warp; s < Ssz; s += 16) {
            float* dst = g_pre0p + ((size_t)cta * Ssz + s) * 512;
#pragma unroll 2
            for (int r = 0; r < 16; ++r) {
                const float4* xr = (const float4*)(x + ((size_t)(b0 + r) * Ssz + s) * Dsz);
                float a = 0.0f;
#pragma unroll
                for (int c2 = 0; c2 < 2; ++c2) {
                    float4 xv[8];
#pragma unroll
                    for (int q = 0; q < 8; ++q) xv[q] = __ldg(xr + c2 * 8 + q);
#pragma unroll
                    for (int q = 0; q < 8; ++q) {
                        float4 w = *(const float4*)(sW + ((c2 * 8 + q) * 32 + lane) * 4);
                        a += w.x * xv[q].x + w.y * xv[q].y + w.z * xv[q].z + w.w * xv[q].w;
                    }
                }
                dst[r * 32 + lane] = a + bsum;
            }
        }
        __syncthreads();
    }

    // ---- one-time weight transpose into SMEM: global [col][k] -> [k][col] ----
    {
        const int col = tid & 31, kq = tid >> 5;   // kq 0..15, 16 k each
        const size_t gbase = (size_t)(h0c + col) * Hsz + kq * 16;
#pragma unroll
        for (int j = 0; j < 4; ++j) {
            float4 a = *(const float4*)(Whh0 + gbase + j * 4);
            float4 b = *(const float4*)(Wih1 + gbase + j * 4);
            float4 c = *(const float4*)(Whh1 + gbase + j * 4);
            const int kb = kq * 16 + j * 4;
            sW0 [(kb + 0) * 32 + col] = a.x; sW0 [(kb + 1) * 32 + col] = a.y;
            sW0 [(kb + 2) * 32 + col] = a.z; sW0 [(kb + 3) * 32 + col] = a.w;
            sWi1[(kb + 0) * 32 + col] = b.x; sWi1[(kb + 1) * 32 + col] = b.y;
            sWi1[(kb + 2) * 32 + col] = b.z; sWi1[(kb + 3) * 32 + col] = b.w;
            sWh1[(kb + 0) * 32 + col] = c.x; sWh1[(kb + 1) * 32 + col] = c.y;
            sWh1[(kb + 2) * 32 + col] = c.z; sWh1[(kb + 3) * 32 + col] = c.w;
        }
    }
    const float bias1 = bih1[h0c + lane] + bhh1[h0c + lane];

    // ---- group-local barrier (8 CTAs of this batch group) ----
#define GROUP_BARRIER(VAL, FENCED) do {                                    \
        if (FENCED) __threadfence();                                       \
        __syncthreads();                                                   \
        if (tid == 0) g_flags[cta] = (VAL);                                \
        if (tid < 8) {                                                     \
            volatile unsigned int* pf = &g_flags[grp8 + tid];              \
            const unsigned int tgt = (VAL);                                \
            while ((int)(*pf - tgt) < 0) { }                               \
        }                                                                  \
        __syncthreads();                                                   \
    } while (0)

    GROUP_BARRIER(1u, true);

    // rank-1 update helper: 3 LDS.128 + 8 independent fma2 per k
#define RANK1(SW, ST, K) do {                                              \
        ulonglong2 w2 = *(const ulonglong2*)((SW) + (K) * 32 + c0);        \
        ulonglong2 hA = *(const ulonglong2*)((ST) + (K) * 32 + 2 * r0);    \
        ulonglong2 hB = *(const ulonglong2*)((ST) + (K) * 32 + 2 * r0 + 4);\
        acc[0] = fma2(hA.x, w2.x, acc[0]);                                 \
        acc[1] = fma2(hA.x, w2.y, acc[1]);                                 \
        acc[2] = fma2(hA.y, w2.x, acc[2]);                                 \
        acc[3] = fma2(hA.y, w2.y, acc[3]);                                 \
        acc[4] = fma2(hB.x, w2.x, acc[4]);                                 \
        acc[5] = fma2(hB.x, w2.y, acc[5]);                                 \
        acc[6] = fma2(hB.y, w2.x, acc[6]);                                 \
        acc[7] = fma2(hB.y, w2.y, acc[7]);                                 \
    } while (0)

    // ================= phase 2: fused two-layer recurrence =================
    for (int i = 0; i <= Ssz; ++i) {
        // ---- stage previous states: transpose + duplicate into SMEM ----
        {
            const int half = tid >> 8;            // 0: h0, 1: h1
            const int t    = tid & 255;
            const int row  = t & 15, kq = t >> 4; // 16 k per thread
            const float* src = half ? (g_h1[i & 1]       + (size_t)(b0 + row) * Hsz + kq * 16)
                                    : (g_h0[(i + 1) & 1] + (size_t)(b0 + row) * Hsz + kq * 16);
            float* dstT = (half ? sH1T : sH0T) + kq * 16 * 32 + 2 * row;
#pragma unroll
            for (int j = 0; j < 4; ++j) {
                float4 v = __ldcg((const float4*)(src + j * 4));
                *(float2*)(dstT + (j * 4 + 0) * 32) = make_float2(v.x, v.x);
                *(float2*)(dstT + (j * 4 + 1) * 32) = make_float2(v.y, v.y);
                *(float2*)(dstT + (j * 4 + 2) * 32) = make_float2(v.z, v.z);
                *(float2*)(dstT + (j * 4 + 3) * 32) = make_float2(v.w, v.w);
            }
        }
        __syncthreads();

        float p[4];
        if (warp < 4) {
            // ---- Whh0 over k-quarter [warp*64, +64) ----
            if (i < Ssz) {
                unsigned long long acc[8] = {0,0,0,0,0,0,0,0};
                const int kb = warp * 64;
#pragma unroll 4
                for (int j = 0; j < 64; ++j) RANK1(sW0, sH0T, kb + j);
                float* red = sRed + warp * 544;
#pragma unroll
                for (int ri = 0; ri < 4; ++ri) {
                    *(unsigned long long*)(red + (r0 + ri) * 34 + c0 + 0) = acc[ri * 2 + 0];
                    *(unsigned long long*)(red + (r0 + ri) * 34 + c0 + 2) = acc[ri * 2 + 1];
                }
            }
        } else if (warp < 12) {
            // ---- Wih1 (with h0T) + Whh1 (with h1T) over k-eighth ----
            if (i >= 1) {
                unsigned long long acc[8] = {0,0,0,0,0,0,0,0};
                const int kb = (warp - 4) * 32;
#pragma unroll 4
                for (int j = 0; j < 32; ++j) RANK1(sWi1, sH0T, kb + j);
#pragma unroll 4
                for (int j = 0; j < 32; ++j) RANK1(sWh1, sH1T, kb + j);
                float* red = sRed + warp * 544;
#pragma unroll
                for (int ri = 0; ri < 4; ++ri) {
                    *(unsigned long long*)(red + (r0 + ri) * 34 + c0 + 0) = acc[ri * 2 + 0];
                    *(unsigned long long*)(red + (r0 + ri) * 34 + c0 + 2) = acc[ri * 2 + 1];
                }
            }
        } else {
            // ---- util: prefetch pre0 for this step's h0 finalize ----
            if (i < Ssz) {
                const float* pp = g_pre0p + ((size_t)cta * Ssz + i) * 512;
#pragma unroll
                for (int rr = 0; rr < 4; ++rr)
                    p[rr] = pp[(uw * 4 + rr) * 32 + lane];
            }
        }
        __syncthreads();

        // ---- finalize (util warps): reduce partials, tanh, store state ----
        bool stored = false;
        if (warp >= 12) {
            if (i < Ssz) {            // h0_i = tanh(pre0 + sum of 4 Whh0 partials)
                float* dst = g_h0[i & 1];
#pragma unroll
                for (int rr = 0; rr < 4; ++rr) {
                    const int r = uw * 4 + rr;
                    float s = p[rr];
#pragma unroll
                    for (int q = 0; q < 4; ++q) s += sRed[q * 544 + r * 34 + lane];
                    __stcg(&dst[(size_t)(b0 + r) * Hsz + h0c + lane], tanh_fast(s));
                }
                stored = true;
            }
            if (i >= 1) {             // h1_{i-1} = tanh(bias + sum of 8 fused partials)
                float* dst = g_h1[(i - 1) & 1];
#pragma unroll
                for (int rr = 0; rr < 4; ++rr) {
                    const int r = uw * 4 + rr;
                    float s = bias1;
#pragma unroll
                    for (int q = 4; q < 12; ++q) s += sRed[q * 544 + r * 34 + lane];
                    __stcg(&dst[(size_t)(b0 + r) * Hsz + h0c + lane], tanh_fast(s));
                }
                stored = true;
            }
        }

        GROUP_BARRIER((unsigned int)(i + 2), stored);
    }

    // ================= phase 3: head (16 CTAs, one per batch group) =================
    if ((cta & 7) == 0 && warp < 8) {
        const float bo = bout[0];
#pragma unroll
        for (int rr = 0; rr < 2; ++rr) {
            const int b = b0 + warp * 2 + rr;
            const float* h = g_h1[(Ssz - 1) & 1] + (size_t)b * Hsz;
            float s = 0.0f;
#pragma unroll
            for (int j = 0; j < 8; ++j)
                s += __ldcg(&h[lane + 32 * j]) * Wout[lane + 32 * j];
#pragma unroll
            for (int o = 16; o > 0; o >>= 1) s += __shfl_down_sync(0xFFFFFFFFu, s, o);
            if (lane == 0) out[b] = 1.0f / (1.0f + expf(-(s + bo)));
        }
    }
#undef GROUP_BARRIER
#undef RANK1
}

// ---------------- launch ----------------
extern "C" void kernel_launch(void* const* d_in, const int* in_sizes, int n_in,
                              void* d_out, int out_size) {
    const float* x    = (const float*)d_in[0];
    const float* Wih0 = (const float*)d_in[1];
    const float* Whh0 = (const float*)d_in[2];
    const float* bih0 = (const float*)d_in[3];
    const float* bhh0 = (const float*)d_in[4];
    const float* Wih1 = (const float*)d_in[5];
    const float* Whh1 = (const float*)d_in[6];
    const float* bih1 = (const float*)d_in[7];
    const float* bhh1 = (const float*)d_in[8];
    const float* Wout = (const float*)d_in[9];
    const float* bout = (const float*)d_in[10];
    float* out = (float*)d_out;

    // smem: 3*8192 (W) + 2*8192 (states) + 12*544 (red) floats = 190,336 B
    const int smem_bytes = (5 * 8192 + 12 * 544) * (int)sizeof(float);
    static int configured = 0;
    if (!configured) {
        cudaFuncSetAttribute(fused_kernel, cudaFuncAttributeMaxDynamicSharedMemorySize, smem_bytes);
        configured = 1;
    }

    init_kernel<<<(Bsz * Hsz + 511) / 512, 512>>>();
    fused_kernel<<<NCTA, NTHR, smem_bytes>>>(x, Wih0, Whh0, bih0, bhh0,
                                             Wih1, Whh1, bih1, bhh1,
                                             Wout, bout, out);
}

// round 11
// speedup vs baseline: 1.0522x; 1.0522x over previous
#include <cuda_runtime.h>
#include <math.h>
#include <stdint.h>

#define Bsz 256
#define Ssz 2048
#define Dsz 64
#define Hsz 256
#define NCTA 128          // persistent CTAs, 1/SM, all co-resident
#define NTHR 512          // 16 warps: 12 compute, finalize spread over all 16
#define WPAD 260          // state row stride (floats)

// ---------------- device scratch ----------------
__device__ float g_pre0p[(size_t)NCTA * Ssz * 512];  // private pre0 [cta][s][row16][lane32]
__device__ float g_h0[2][Bsz * Hsz];                 // layer-0 state, double buffered
__device__ float g_h1[2][Bsz * Hsz];                 // layer-1 state, double buffered
__device__ unsigned int g_flags[NCTA];               // barrier flags (zeroed by init)

__device__ __forceinline__ float tanh_fast(float x) {
    float y; asm("tanh.approx.f32 %0, %1;" : "=f"(y) : "f"(x)); return y;
}
__device__ __forceinline__ unsigned long long fma2(unsigned long long a,
                                                   unsigned long long b,
                                                   unsigned long long c) {
    unsigned long long d;
    asm("fma.rn.f32x2 %0, %1, %2, %3;" : "=l"(d) : "l"(a), "l"(b), "l"(c));
    return d;
}
__device__ __forceinline__ unsigned long long add2(unsigned long long a,
                                                   unsigned long long b) {
    unsigned long long d;
    asm("add.rn.f32x2 %0, %1, %2;" : "=l"(d) : "l"(a), "l"(b));
    return d;
}
__device__ __forceinline__ float hsum2(unsigned long long a) {
    float2 f = *reinterpret_cast<float2*>(&a);
    return f.x + f.y;
}

// ---------------- init: zero flags + seed states ----------------
__global__ void init_kernel() {
    const int idx = blockIdx.x * blockDim.x + threadIdx.x;
    if (idx < NCTA) g_flags[idx] = 0u;
    if (idx < Bsz * Hsz) {
        g_h0[1][idx] = 0.0f;
        g_h1[1][idx] = 0.0f;
    }
}

__global__ void __launch_bounds__(NTHR, 1)
fused_kernel(const float* __restrict__ x,
             const float* __restrict__ Wih0,
             const float* __restrict__ Whh0,
             const float* __restrict__ bih0,
             const float* __restrict__ bhh0,
             const float* __restrict__ Wih1,
             const float* __restrict__ Whh1,
             const float* __restrict__ bih1,
             const float* __restrict__ bhh1,
             const float* __restrict__ Wout,
             const float* __restrict__ bout,
             float* __restrict__ out) {
    extern __shared__ float smem[];
    float* sH0  = smem;                      // [16][WPAD]  h0_{i-1}   (pre0 reuses as sW)
    float* sH1  = sH0 + 16 * WPAD;           // [16][WPAD]  h1_{i-2}
    float* sRed = sH1 + 16 * WPAD;           // 12 tiles of [16][33] partials

    const int tid  = threadIdx.x;
    const int cta  = blockIdx.x;
    const int grp8 = (cta >> 3) * 8;
    const int b0   = (cta >> 3) * 16;         // 16 batch rows
    const int h0c  = (cta & 7) * 32;          // 32 h columns
    const int lane = tid & 31;
    const int warp = tid >> 5;                // 0..15
    // compute warps 0..11: m = warp>>2 (0=Whh0,1=Wih1,2=Whh1), kQ = warp&3 (=SMSP)
    const int m  = warp >> 2;
    const int kQ = warp & 3;

    // ================= phase 1: pre0_priv = x @ Wih0^T + (b_ih0+b_hh0) =================
    {
        float* sW = sH0;   // 2048 floats, overwritten later by state staging
        for (int it = tid; it < 32 * 16; it += NTHR) {
            const int col = it >> 4, kq = it & 15;
            *(float4*)(sW + (kq * 32 + col) * 4) =
                *(const float4*)(Wih0 + (size_t)(h0c + col) * Dsz + kq * 4);
        }
        __syncthreads();
        const float bsum = bih0[h0c + lane] + bhh0[h0c + lane];

        for (int s = warp; s < Ssz; s += 16) {
            float* dst = g_pre0p + ((size_t)cta * Ssz + s) * 512;
#pragma unroll 2
            for (int r = 0; r < 16; ++r) {
                const float4* xr = (const float4*)(x + ((size_t)(b0 + r) * Ssz + s) * Dsz);
                float a = 0.0f;
#pragma unroll
                for (int c2 = 0; c2 < 2; ++c2) {
                    float4 xv[8];
#pragma unroll
                    for (int q = 0; q < 8; ++q) xv[q] = __ldg(xr + c2 * 8 + q);
#pragma unroll
                    for (int q = 0; q < 8; ++q) {
                        float4 w = *(const float4*)(sW + ((c2 * 8 + q) * 32 + lane) * 4);
                        a += w.x * xv[q].x + w.y * xv[q].y + w.z * xv[q].z + w.w * xv[q].w;
                    }
                }
                dst[r * 32 + lane] = a + bsum;
            }
        }
        __syncthreads();   // sW region about to be reused
    }

    // ---- compute warps: load own 64 weights into registers (persist all steps) ----
    unsigned long long w0[16], w1[16];
    if (warp < 12) {
        const float* Wsrc = (m == 0) ? Whh0 : (m == 1) ? Wih1 : Whh1;
        const float* base = Wsrc + (size_t)(h0c + lane) * Hsz + kQ * 64;
#pragma unroll
        for (int j = 0; j < 16; ++j) {
            ulonglong2 t = *(const ulonglong2*)(base + j * 4);
            w0[j] = t.x; w1[j] = t.y;
        }
    }
    const float bias1 = bih1[h0c + lane] + bhh1[h0c + lane];

    // ---- group-local barrier (sync the 8 CTAs of this batch group) ----
#define GROUP_BARRIER(VAL, FENCED) do {                                    \
        if (FENCED) __threadfence();                                       \
        __syncthreads();                                                   \
        if (tid == 0) g_flags[cta] = (VAL);                                \
        if (tid < 8) {                                                     \
            volatile unsigned int* pf = &g_flags[grp8 + tid];              \
            const unsigned int tgt = (VAL);                                \
            while ((int)(*pf - tgt) < 0) { }                               \
        }                                                                  \
        __syncthreads();                                                   \
    } while (0)

    GROUP_BARRIER(1u, true);   // pre0 + init seeds visible

    // ================= phase 2: fused two-layer recurrence =================
    for (int i = 0; i <= Ssz; ++i) {
        // ---- stage previous states: 256 threads per half, FULL 256-float rows ----
        {
            const int half = tid >> 8;            // 0: h0, 1: h1
            const int t    = tid & 255;
            const int row  = t >> 4, c16 = t & 15;
            const float* src = half ? (g_h1[i & 1]       + (size_t)(b0 + row) * Hsz)
                                    : (g_h0[(i + 1) & 1] + (size_t)(b0 + row) * Hsz);
            float* dst = (half ? sH1 : sH0) + row * WPAD;
#pragma unroll
            for (int q = 0; q < 4; ++q)
                *(float4*)(dst + (c16 + q * 16) * 4) =
                    __ldcg((const float4*)(src + (c16 + q * 16) * 4));
        }
        // ---- every warp prefetches ITS finalize row's pre0 (hidden behind compute) ----
        float p = 0.0f;
        if (i < Ssz)
            p = g_pre0p[((size_t)cta * Ssz + i) * 512 + warp * 32 + lane];
        __syncthreads();

        // ---- compute partials: 12 warps, 4 independent fma2 chains per row ----
        if (warp < 12) {
            const bool active = (m == 0) ? (i < Ssz) : (i >= 1);
            if (active) {
                const float* Sp = ((m == 2) ? sH1 : sH0) + kQ * 64;
                float* red = sRed + (m * 4 + kQ) * 528;
#pragma unroll 2
                for (int r = 0; r < 16; ++r) {
                    unsigned long long a0 = 0ull, a1 = 0ull, b0acc = 0ull, b1acc = 0ull;
                    const ulonglong2* vp = (const ulonglong2*)(Sp + r * WPAD);
#pragma unroll
                    for (int j = 0; j < 8; ++j) {
                        ulonglong2 v0 = vp[j];
                        ulonglong2 v1 = vp[j + 8];
                        a0    = fma2(w0[j],     v0.x, a0);
                        a1    = fma2(w1[j],     v0.y, a1);
                        b0acc = fma2(w0[j + 8], v1.x, b0acc);
                        b1acc = fma2(w1[j + 8], v1.y, b1acc);
                    }
                    red[r * 33 + lane] = hsum2(add2(add2(a0, b0acc), add2(a1, b1acc)));
                }
            }
        }
        __syncthreads();

        // ---- finalize: warp w handles row w of BOTH layers (parallel epilogue) ----
        {
            const int r = warp;
            if (i < Ssz) {            // h0_i = tanh(pre0 + 4 Whh0 partials)
                float s = p;
#pragma unroll
                for (int q = 0; q < 4; ++q) s += sRed[q * 528 + r * 33 + lane];
                __stcg(&g_h0[i & 1][(size_t)(b0 + r) * Hsz + h0c + lane], tanh_fast(s));
            }
            if (i >= 1) {             // h1_{i-1} = tanh(bias + 8 fused partials)
                float s = bias1;
#pragma unroll
                for (int q = 4; q < 12; ++q) s += sRed[q * 528 + r * 33 + lane];
                __stcg(&g_h1[(i - 1) & 1][(size_t)(b0 + r) * Hsz + h0c + lane], tanh_fast(s));
            }
        }

        GROUP_BARRIER((unsigned int)(i + 2), true);
    }

    // ================= phase 3: head (16 CTAs, one per batch group) =================
    if ((cta & 7) == 0 && warp < 8) {
        const float bo = bout[0];
#pragma unroll
        for (int rr = 0; rr < 2; ++rr) {
            const int b = b0 + warp * 2 + rr;
            const float* h = g_h1[(Ssz - 1) & 1] + (size_t)b * Hsz;
            float s = 0.0f;
#pragma unroll
            for (int j = 0; j < 8; ++j)
                s += __ldcg(&h[lane + 32 * j]) * Wout[lane + 32 * j];
#pragma unroll
            for (int o = 16; o > 0; o >>= 1) s += __shfl_down_sync(0xFFFFFFFFu, s, o);
            if (lane == 0) out[b] = 1.0f / (1.0f + expf(-(s + bo)));
        }
    }
#undef GROUP_BARRIER
}

// ---------------- launch ----------------
extern "C" void kernel_launch(void* const* d_in, const int* in_sizes, int n_in,
                              void* d_out, int out_size) {
    const float* x    = (const float*)d_in[0];
    const float* Wih0 = (const float*)d_in[1];
    const float* Whh0 = (const float*)d_in[2];
    const float* bih0 = (const float*)d_in[3];
    const float* bhh0 = (const float*)d_in[4];
    const float* Wih1 = (const float*)d_in[5];
    const float* Whh1 = (const float*)d_in[6];
    const float* bih1 = (const float*)d_in[7];
    const float* bhh1 = (const float*)d_in[8];
    const float* Wout = (const float*)d_in[9];
    const float* bout = (const float*)d_in[10];
    float* out = (float*)d_out;

    // smem: 2*16*WPAD + 12*16*33 floats = 8320 + 6336 = 14656 floats = 58,624 B
    const int smem_bytes = (2 * 16 * WPAD + 12 * 16 * 33) * (int)sizeof(float);
    static int configured = 0;
    if (!configured) {
        cudaFuncSetAttribute(fused_kernel, cudaFuncAttributeMaxDynamicSharedMemorySize, smem_bytes);
        configured = 1;
    }

    init_kernel<<<(Bsz * Hsz + 511) / 512, 512>>>();
    fused_kernel<<<NCTA, NTHR, smem_bytes>>>(x, Wih0, Whh0, bih0, bhh0,
                                             Wih1, Whh1, bih1, bhh1,
                                             Wout, bout, out);
}

// round 12
// speedup vs baseline: 1.2405x; 1.1789x over previous
#include <cuda_runtime.h>
#include <math.h>
#include <stdint.h>

#define Bsz 256
#define Ssz 2048
#define Dsz 64
#define Hsz 256
#define NCTA 128          // persistent CTAs, 1/SM, all co-resident
#define NTHR 512          // 16 warps; warp w owns k-slice [16w,16w+16) and row w
#define WPAD 260          // state row stride (floats)

// ---------------- device scratch ----------------
__device__ float g_pre0p[(size_t)NCTA * Ssz * 512];  // private pre0 [cta][s][row16][lane32]
__device__ float g_h0[2][Bsz * Hsz];                 // layer-0 state, double buffered
__device__ float g_h1[2][Bsz * Hsz];                 // layer-1 state, double buffered
__device__ unsigned int g_flags[NCTA];               // barrier flags (zeroed by init)

__device__ __forceinline__ float tanh_fast(float x) {
    float y; asm("tanh.approx.f32 %0, %1;" : "=f"(y) : "f"(x)); return y;
}
__device__ __forceinline__ unsigned long long fma2(unsigned long long a,
                                                   unsigned long long b,
                                                   unsigned long long c) {
    unsigned long long d;
    asm("fma.rn.f32x2 %0, %1, %2, %3;" : "=l"(d) : "l"(a), "l"(b), "l"(c));
    return d;
}
__device__ __forceinline__ unsigned long long add2(unsigned long long a,
                                                   unsigned long long b) {
    unsigned long long d;
    asm("add.rn.f32x2 %0, %1, %2;" : "=l"(d) : "l"(a), "l"(b));
    return d;
}
__device__ __forceinline__ float hsum2(unsigned long long a) {
    float2 f = *reinterpret_cast<float2*>(&a);
    return f.x + f.y;
}

// ---------------- init: zero flags + seed states ----------------
__global__ void init_kernel() {
    const int idx = blockIdx.x * blockDim.x + threadIdx.x;
    if (idx < NCTA) g_flags[idx] = 0u;
    if (idx < Bsz * Hsz) {
        g_h1[0][idx] = 0.0f;
        g_h1[1][idx] = 0.0f;
    }
}

__global__ void __launch_bounds__(NTHR, 1)
fused_kernel(const float* __restrict__ x,
             const float* __restrict__ Wih0,
             const float* __restrict__ Whh0,
             const float* __restrict__ bih0,
             const float* __restrict__ bhh0,
             const float* __restrict__ Wih1,
             const float* __restrict__ Whh1,
             const float* __restrict__ bih1,
             const float* __restrict__ bhh1,
             const float* __restrict__ Wout,
             const float* __restrict__ bout,
             float* __restrict__ out) {
    extern __shared__ float smem[];
    float* sH0  = smem;                      // [16][WPAD]  h0_{i-1}
    float* sH1  = sH0 + 16 * WPAD;           // [16][WPAD]  h1_{i-2}
    float* sRed = sH1 + 16 * WPAD;           // 16 tiles of [16][33] partials

    const int tid  = threadIdx.x;
    const int cta  = blockIdx.x;
    const int grp8 = (cta >> 3) * 8;
    const int b0   = (cta >> 3) * 16;         // 16 batch rows
    const int h0c  = (cta & 7) * 32;          // 32 h columns
    const int lane = tid & 31;
    const int warp = tid >> 5;                // 0..15: k-slice AND finalize row

    // staging map: warp w stages row w (two float4 per thread)
    const int srow = warp, sc = lane;

    // ================= phase 1: pre0_priv = x @ Wih0^T + (b_ih0+b_hh0) =================
    {
        float* sW = sH0;   // scratch, re-zeroed later
        for (int it = tid; it < 32 * 16; it += NTHR) {
            const int col = it >> 4, kq = it & 15;
            *(float4*)(sW + (kq * 32 + col) * 4) =
                *(const float4*)(Wih0 + (size_t)(h0c + col) * Dsz + kq * 4);
        }
        __syncthreads();
        const float bsum = bih0[h0c + lane] + bhh0[h0c + lane];

        for (int s = warp; s < Ssz; s += 16) {
            float* dst = g_pre0p + ((size_t)cta * Ssz + s) * 512;
#pragma unroll 2
            for (int r = 0; r < 16; ++r) {
                const float4* xr = (const float4*)(x + ((size_t)(b0 + r) * Ssz + s) * Dsz);
                float a = 0.0f;
#pragma unroll
                for (int c2 = 0; c2 < 2; ++c2) {
                    float4 xv[8];
#pragma unroll
                    for (int q = 0; q < 8; ++q) xv[q] = __ldg(xr + c2 * 8 + q);
#pragma unroll
                    for (int q = 0; q < 8; ++q) {
                        float4 w = *(const float4*)(sW + ((c2 * 8 + q) * 32 + lane) * 4);
                        a += w.x * xv[q].x + w.y * xv[q].y + w.z * xv[q].z + w.w * xv[q].w;
                    }
                }
                dst[r * 32 + lane] = a + bsum;
            }
        }
        __syncthreads();
    }

    // ---- per-lane register weights: col = h0c+lane, k-slice [warp*16, +16) ----
    unsigned long long wA[8], wI[8], wH[8];
    {
        const size_t off = (size_t)(h0c + lane) * Hsz + warp * 16;
#pragma unroll
        for (int j = 0; j < 4; ++j) {
            ulonglong2 a = *(const ulonglong2*)(Whh0 + off + j * 4);
            ulonglong2 b = *(const ulonglong2*)(Wih1 + off + j * 4);
            ulonglong2 c = *(const ulonglong2*)(Whh1 + off + j * 4);
            wA[j * 2] = a.x; wA[j * 2 + 1] = a.y;
            wI[j * 2] = b.x; wI[j * 2 + 1] = b.y;
            wH[j * 2] = c.x; wH[j * 2 + 1] = c.y;
        }
    }
    const float bias1 = bih1[h0c + lane] + bhh1[h0c + lane];

    // ---- zero sH0 (= h0_{-1}) and announce readiness (flag = 1) ----
    for (int it = tid; it < 16 * WPAD; it += NTHR) sH0[it] = 0.0f;
    __syncthreads();
    if (tid == 0) {
        __threadfence();
        *(volatile unsigned int*)&g_flags[cta] = 1u;
    }

#define POLL(VAL) do {                                                     \
        if (tid < 8) {                                                     \
            volatile unsigned int* pf = &g_flags[grp8 + tid];              \
            const unsigned int tgt = (VAL);                                \
            while (*pf < tgt) { }                                          \
        }                                                                  \
    } while (0)

    // p for iteration 0 (row = warp)
    float p = (Ssz > 0) ? g_pre0p[(size_t)cta * Ssz * 512 + warp * 32 + lane] : 0.0f;

    // ================= phase 2: pipelined two-layer recurrence =================
    for (int i = 0; i <= Ssz; ++i) {
        const unsigned int f_h0 = 2u * i + 2u;   // peers' h0_i stored
        const unsigned int f_h1 = 2u * i + 3u;   // peers' h1_{i-1} stored
        const unsigned int f_h1prev = 2u * i + 1u; // peers' h1_{i-2} stored (prev iter)

        // ---- A: h0_i partials over own 16-k slice (all 16 warps) ----
        if (i < Ssz) {
            float* red = sRed + warp * 528;
            const float* S = sH0 + warp * 16;
#pragma unroll 4
            for (int r = 0; r < 16; ++r) {
                const ulonglong2* hp = (const ulonglong2*)(S + r * WPAD);
                ulonglong2 h01 = hp[0], h23 = hp[1], h45 = hp[2], h67 = hp[3];
                unsigned long long a0 = fma2(wA[0], h01.x, 0ull);
                unsigned long long a1 = fma2(wA[1], h01.y, 0ull);
                unsigned long long a2 = fma2(wA[2], h23.x, 0ull);
                unsigned long long a3 = fma2(wA[3], h23.y, 0ull);
                a0 = fma2(wA[4], h45.x, a0);
                a1 = fma2(wA[5], h45.y, a1);
                a2 = fma2(wA[6], h67.x, a2);
                a3 = fma2(wA[7], h67.y, a3);
                red[r * 33 + lane] = hsum2(add2(add2(a0, a1), add2(a2, a3)));
            }
        }
        __syncthreads();   // S1: h0 partials ready

        // ---- B: finalize h0_i (warp w -> row w), store, fence ----
        if (i < Ssz) {
            float s = p;
#pragma unroll
            for (int q = 0; q < 16; ++q) s += sRed[q * 528 + warp * 33 + lane];
            __stcg(&g_h0[i & 1][(size_t)(b0 + warp) * Hsz + h0c + lane], tanh_fast(s));
            __threadfence();
        }
        POLL(f_h1prev);    // h1_{i-2} available (set by peers one iteration ago: free)
        __syncthreads();   // S2: stores fenced + poll done
        if (tid == 0) *(volatile unsigned int*)&g_flags[cta] = f_h0;

        // ---- stage h1_{i-2} -> sH1 (sH1 idle since last iteration's C/D) ----
        {
            const float* src = g_h1[i & 1] + (size_t)(b0 + srow) * Hsz;   // (i-2)&1 == i&1
            float* dst = sH1 + srow * WPAD;
            *(float4*)(dst + sc * 4)        = __ldcg((const float4*)(src + sc * 4));
            *(float4*)(dst + (sc + 32) * 4) = __ldcg((const float4*)(src + (sc + 32) * 4));
        }
        __syncthreads();   // S3: sH1 ready

        // ---- C: h1_{i-1} partials (Wih1 on sH0, Whh1 on sH1) ----
        if (i >= 1) {
            float* red = sRed + warp * 528;
            const float* S0 = sH0 + warp * 16;
            const float* S1 = sH1 + warp * 16;
#pragma unroll 2
            for (int r = 0; r < 16; ++r) {
                const ulonglong2* hp0 = (const ulonglong2*)(S0 + r * WPAD);
                const ulonglong2* hp1 = (const ulonglong2*)(S1 + r * WPAD);
                ulonglong2 u01 = hp0[0], u23 = hp0[1], u45 = hp0[2], u67 = hp0[3];
                ulonglong2 v01 = hp1[0], v23 = hp1[1], v45 = hp1[2], v67 = hp1[3];
                unsigned long long a0 = fma2(wI[0], u01.x, 0ull);
                unsigned long long a1 = fma2(wI[1], u01.y, 0ull);
                unsigned long long a2 = fma2(wI[2], u23.x, 0ull);
                unsigned long long a3 = fma2(wI[3], u23.y, 0ull);
                a0 = fma2(wI[4], u45.x, a0);
                a1 = fma2(wI[5], u45.y, a1);
                a2 = fma2(wI[6], u67.x, a2);
                a3 = fma2(wI[7], u67.y, a3);
                a0 = fma2(wH[0], v01.x, a0);
                a1 = fma2(wH[1], v01.y, a1);
                a2 = fma2(wH[2], v23.x, a2);
                a3 = fma2(wH[3], v23.y, a3);
                a0 = fma2(wH[4], v45.x, a0);
                a1 = fma2(wH[5], v45.y, a1);
                a2 = fma2(wH[6], v67.x, a2);
                a3 = fma2(wH[7], v67.y, a3);
                red[r * 33 + lane] = hsum2(add2(add2(a0, a1), add2(a2, a3)));
            }
        }
        __syncthreads();   // S4: h1 partials ready

        // ---- D: finalize h1_{i-1}, store, fence ----
        if (i >= 1) {
            float s = bias1;
#pragma unroll
            for (int q = 0; q < 16; ++q) s += sRed[q * 528 + warp * 33 + lane];
            __stcg(&g_h1[(i - 1) & 1][(size_t)(b0 + warp) * Hsz + h0c + lane], tanh_fast(s));
            __threadfence();
        }
        if (i < Ssz) POLL(f_h0);   // peers' h0_i — hidden behind our C+D
        __syncthreads();           // S5
        if (tid == 0) *(volatile unsigned int*)&g_flags[cta] = f_h1;

        // ---- E: stage h0_i -> sH0 ; prefetch next pre0 ----
        if (i < Ssz) {
            const float* src = g_h0[i & 1] + (size_t)(b0 + srow) * Hsz;
            float* dst = sH0 + srow * WPAD;
            *(float4*)(dst + sc * 4)        = __ldcg((const float4*)(src + sc * 4));
            *(float4*)(dst + (sc + 32) * 4) = __ldcg((const float4*)(src + (sc + 32) * 4));
            if (i + 1 < Ssz)
                p = g_pre0p[((size_t)cta * Ssz + i + 1) * 512 + warp * 32 + lane];
        }
        __syncthreads();   // S6: sH0 ready for next iteration
    }

    // ================= phase 3: head (16 CTAs, one per batch group) =================
    if ((cta & 7) == 0) {
        POLL(2u * Ssz + 3u);
        __syncthreads();
        if (warp < 8) {
            const float bo = bout[0];
#pragma unroll
            for (int rr = 0; rr < 2; ++rr) {
                const int b = b0 + warp * 2 + rr;
                const float* h = g_h1[(Ssz - 1) & 1] + (size_t)b * Hsz;
                float s = 0.0f;
#pragma unroll
                for (int j = 0; j < 8; ++j)
                    s += __ldcg(&h[lane + 32 * j]) * Wout[lane + 32 * j];
#pragma unroll
                for (int o = 16; o > 0; o >>= 1) s += __shfl_down_sync(0xFFFFFFFFu, s, o);
                if (lane == 0) out[b] = 1.0f / (1.0f + expf(-(s + bo)));
            }
        }
    }
#undef POLL
}

// ---------------- launch ----------------
extern "C" void kernel_launch(void* const* d_in, const int* in_sizes, int n_in,
                              void* d_out, int out_size) {
    const float* x    = (const float*)d_in[0];
    const float* Wih0 = (const float*)d_in[1];
    const float* Whh0 = (const float*)d_in[2];
    const float* bih0 = (const float*)d_in[3];
    const float* bhh0 = (const float*)d_in[4];
    const float* Wih1 = (const float*)d_in[5];
    const float* Whh1 = (const float*)d_in[6];
    const float* bih1 = (const float*)d_in[7];
    const float* bhh1 = (const float*)d_in[8];
    const float* Wout = (const float*)d_in[9];
    const float* bout = (const float*)d_in[10];
    float* out = (float*)d_out;

    // smem: 2*16*WPAD + 16*528 floats = 8320 + 8448 = 16768 floats = 67,072 B
    const int smem_bytes = (2 * 16 * WPAD + 16 * 528) * (int)sizeof(float);
    static int configured = 0;
    if (!configured) {
        cudaFuncSetAttribute(fused_kernel, cudaFuncAttributeMaxDynamicSharedMemorySize, smem_bytes);
        configured = 1;
    }

    init_kernel<<<(Bsz * Hsz + 511) / 512, 512>>>();
    fused_kernel<<<NCTA, NTHR, smem_bytes>>>(x, Wih0, Whh0, bih0, bhh0,
                                             Wih1, Whh1, bih1, bhh1,
                                             Wout, bout, out);
}

// round 13
// speedup vs baseline: 1.3626x; 1.0984x over previous
#include <cuda_runtime.h>
#include <math.h>
#include <stdint.h>

#define Bsz 256
#define Ssz 2048
#define Dsz 64
#define Hsz 256
#define NCTA 128          // persistent CTAs, 1/SM, all co-resident
#define NTHR 512          // 16 warps; warp w owns k-slice [16w,16w+16) and row w
#define WPAD 260          // state row stride (floats)

// ---------------- device scratch ----------------
__device__ float g_pre0p[(size_t)NCTA * Ssz * 512];  // private pre0 [cta][s][row16][lane32]
__device__ float g_h0[2][Bsz * Hsz];                 // layer-0 state, double buffered
__device__ float g_h1[2][Bsz * Hsz];                 // layer-1 state, double buffered
__device__ unsigned int g_flags[NCTA];               // barrier flags (zeroed by init)

__device__ __forceinline__ float tanh_fast(float x) {
    float y; asm("tanh.approx.f32 %0, %1;" : "=f"(y) : "f"(x)); return y;
}
__device__ __forceinline__ unsigned long long fma2(unsigned long long a,
                                                   unsigned long long b,
                                                   unsigned long long c) {
    unsigned long long d;
    asm("fma.rn.f32x2 %0, %1, %2, %3;" : "=l"(d) : "l"(a), "l"(b), "l"(c));
    return d;
}
__device__ __forceinline__ unsigned long long add2(unsigned long long a,
                                                   unsigned long long b) {
    unsigned long long d;
    asm("add.rn.f32x2 %0, %1, %2;" : "=l"(d) : "l"(a), "l"(b));
    return d;
}
__device__ __forceinline__ float hsum2(unsigned long long a) {
    float2 f = *reinterpret_cast<float2*>(&a);
    return f.x + f.y;
}
// release publish / acquire poll (cumulative: carries all CTA stores via bar.sync)
__device__ __forceinline__ void st_release(unsigned int* p, unsigned int v) {
    asm volatile("st.release.gpu.global.u32 [%0], %1;" :: "l"(p), "r"(v) : "memory");
}
__device__ __forceinline__ unsigned int ld_acquire(const unsigned int* p) {
    unsigned int v;
    asm volatile("ld.acquire.gpu.global.u32 %0, [%1];" : "=r"(v) : "l"(p) : "memory");
    return v;
}

// ---------------- init: zero flags + seed states ----------------
__global__ void init_kernel() {
    const int idx = blockIdx.x * blockDim.x + threadIdx.x;
    if (idx < NCTA) g_flags[idx] = 0u;
    if (idx < Bsz * Hsz) {
        g_h1[0][idx] = 0.0f;
        g_h1[1][idx] = 0.0f;
    }
}

__global__ void __launch_bounds__(NTHR, 1)
fused_kernel(const float* __restrict__ x,
             const float* __restrict__ Wih0,
             const float* __restrict__ Whh0,
             const float* __restrict__ bih0,
             const float* __restrict__ bhh0,
             const float* __restrict__ Wih1,
             const float* __restrict__ Whh1,
             const float* __restrict__ bih1,
             const float* __restrict__ bhh1,
             const float* __restrict__ Wout,
             const float* __restrict__ bout,
             float* __restrict__ out) {
    extern __shared__ float smem[];
    float* sH0   = smem;                     // [16][WPAD]  h0_{i-1}
    float* sH1   = sH0 + 16 * WPAD;          // [16][WPAD]  h1_{i-2}
    float* sRedA = sH1 + 16 * WPAD;          // 16 tiles [16][33]: A partials, then C2
    float* sRedB = sRedA + 16 * 528;         // 16 tiles [16][33]: C1 partials

    const int tid  = threadIdx.x;
    const int cta  = blockIdx.x;
    const int grp8 = (cta >> 3) * 8;
    const int b0   = (cta >> 3) * 16;         // 16 batch rows
    const int h0c  = (cta & 7) * 32;          // 32 h columns
    const int lane = tid & 31;
    const int warp = tid >> 5;                // 0..15: k-slice AND finalize row

    const int srow = warp, sc = lane;         // staging: warp w stages row w

    // ================= phase 1: pre0_priv = x @ Wih0^T + (b_ih0+b_hh0) =================
    {
        float* sW = sH0;   // scratch, re-zeroed later
        for (int it = tid; it < 32 * 16; it += NTHR) {
            const int col = it >> 4, kq = it & 15;
            *(float4*)(sW + (kq * 32 + col) * 4) =
                *(const float4*)(Wih0 + (size_t)(h0c + col) * Dsz + kq * 4);
        }
        __syncthreads();
        const float bsum = bih0[h0c + lane] + bhh0[h0c + lane];

        for (int s = warp; s < Ssz; s += 16) {
            float* dst = g_pre0p + ((size_t)cta * Ssz + s) * 512;
#pragma unroll 2
            for (int r = 0; r < 16; ++r) {
                const float4* xr = (const float4*)(x + ((size_t)(b0 + r) * Ssz + s) * Dsz);
                float a = 0.0f;
#pragma unroll
                for (int c2 = 0; c2 < 2; ++c2) {
                    float4 xv[8];
#pragma unroll
                    for (int q = 0; q < 8; ++q) xv[q] = __ldg(xr + c2 * 8 + q);
#pragma unroll
                    for (int q = 0; q < 8; ++q) {
                        float4 w = *(const float4*)(sW + ((c2 * 8 + q) * 32 + lane) * 4);
                        a += w.x * xv[q].x + w.y * xv[q].y + w.z * xv[q].z + w.w * xv[q].w;
                    }
                }
                dst[r * 32 + lane] = a + bsum;
            }
        }
    }

    // ---- per-lane register weights: col = h0c+lane, k-slice [warp*16, +16) ----
    unsigned long long wA[8], wI[8], wH[8];
    {
        const size_t off = (size_t)(h0c + lane) * Hsz + warp * 16;
#pragma unroll
        for (int j = 0; j < 4; ++j) {
            ulonglong2 a = *(const ulonglong2*)(Whh0 + off + j * 4);
            ulonglong2 b = *(const ulonglong2*)(Wih1 + off + j * 4);
            ulonglong2 c = *(const ulonglong2*)(Whh1 + off + j * 4);
            wA[j * 2] = a.x; wA[j * 2 + 1] = a.y;
            wI[j * 2] = b.x; wI[j * 2 + 1] = b.y;
            wH[j * 2] = c.x; wH[j * 2 + 1] = c.y;
        }
    }
    const float bias1 = bih1[h0c + lane] + bhh1[h0c + lane];

    // ---- zero sH0 (= h0_{-1}); publish readiness (flag = 1) ----
    __syncthreads();   // pre0's sW use done
    for (int it = tid; it < 16 * WPAD; it += NTHR) sH0[it] = 0.0f;
    __syncthreads();
    if (tid == 0) st_release(&g_flags[cta], 1u);

#define POLL(VAL) do {                                                     \
        if (tid < 8) {                                                     \
            const unsigned int tgt = (VAL);                                \
            while (ld_acquire(&g_flags[grp8 + tid]) < tgt) { }             \
        }                                                                  \
    } while (0)

    float p = g_pre0p[(size_t)cta * Ssz * 512 + warp * 32 + lane];   // pre0 for i=0

    // ================= phase 2: pipelined two-layer recurrence =================
    for (int i = 0; i <= Ssz; ++i) {
        // ---- A: h0_i partials over own 16-k slice ----
        if (i < Ssz) {
            float* red = sRedA + warp * 528;
            const float* S = sH0 + warp * 16;
#pragma unroll 4
            for (int r = 0; r < 16; ++r) {
                const ulonglong2* hp = (const ulonglong2*)(S + r * WPAD);
                ulonglong2 h01 = hp[0], h23 = hp[1], h45 = hp[2], h67 = hp[3];
                unsigned long long a0 = fma2(wA[0], h01.x, 0ull);
                unsigned long long a1 = fma2(wA[1], h01.y, 0ull);
                unsigned long long a2 = fma2(wA[2], h23.x, 0ull);
                unsigned long long a3 = fma2(wA[3], h23.y, 0ull);
                a0 = fma2(wA[4], h45.x, a0);
                a1 = fma2(wA[5], h45.y, a1);
                a2 = fma2(wA[6], h67.x, a2);
                a3 = fma2(wA[7], h67.y, a3);
                red[r * 33 + lane] = hsum2(add2(add2(a0, a1), add2(a2, a3)));
            }
        }
        __syncthreads();   // S1

        // ---- B: finalize h0_i (warp w -> row w); poll h1_{i-2} availability ----
        if (i < Ssz) {
            float s = p;
#pragma unroll
            for (int q = 0; q < 16; ++q) s += sRedA[q * 528 + warp * 33 + lane];
            __stcg(&g_h0[i & 1][(size_t)(b0 + warp) * Hsz + h0c + lane], tanh_fast(s));
        }
        POLL(2u * i + 1u);
        __syncthreads();   // S2
        if (tid == 0) st_release(&g_flags[cta], 2u * i + 2u);   // publish h0_i

        // ---- C1: Wih1 (x) h0_{i-1}; h1-staging LDGs fly underneath ----
        float4 e0, e1;
        {
            const float* src = g_h1[i & 1] + (size_t)(b0 + srow) * Hsz;  // h1_{i-2}
            e0 = __ldcg((const float4*)(src + sc * 4));
            e1 = __ldcg((const float4*)(src + (sc + 32) * 4));
        }
        if (i >= 1) {
            float* red = sRedB + warp * 528;
            const float* S = sH0 + warp * 16;
#pragma unroll 4
            for (int r = 0; r < 16; ++r) {
                const ulonglong2* hp = (const ulonglong2*)(S + r * WPAD);
                ulonglong2 h01 = hp[0], h23 = hp[1], h45 = hp[2], h67 = hp[3];
                unsigned long long a0 = fma2(wI[0], h01.x, 0ull);
                unsigned long long a1 = fma2(wI[1], h01.y, 0ull);
                unsigned long long a2 = fma2(wI[2], h23.x, 0ull);
                unsigned long long a3 = fma2(wI[3], h23.y, 0ull);
                a0 = fma2(wI[4], h45.x, a0);
                a1 = fma2(wI[5], h45.y, a1);
                a2 = fma2(wI[6], h67.x, a2);
                a3 = fma2(wI[7], h67.y, a3);
                red[r * 33 + lane] = hsum2(add2(add2(a0, a1), add2(a2, a3)));
            }
        }
        {   // store staged h1_{i-2} row
            float* dst = sH1 + srow * WPAD;
            *(float4*)(dst + sc * 4)        = e0;
            *(float4*)(dst + (sc + 32) * 4) = e1;
        }
        __syncthreads();   // S3

        // ---- C2: Whh1 (x) h1_{i-2}; poll peers' h0_i (for E) ----
        if (i >= 1) {
            float* red = sRedA + warp * 528;     // A tiles consumed at B: reuse
            const float* S = sH1 + warp * 16;
#pragma unroll 4
            for (int r = 0; r < 16; ++r) {
                const ulonglong2* hp = (const ulonglong2*)(S + r * WPAD);
                ulonglong2 h01 = hp[0], h23 = hp[1], h45 = hp[2], h67 = hp[3];
                unsigned long long a0 = fma2(wH[0], h01.x, 0ull);
                unsigned long long a1 = fma2(wH[1], h01.y, 0ull);
                unsigned long long a2 = fma2(wH[2], h23.x, 0ull);
                unsigned long long a3 = fma2(wH[3], h23.y, 0ull);
                a0 = fma2(wH[4], h45.x, a0);
                a1 = fma2(wH[5], h45.y, a1);
                a2 = fma2(wH[6], h67.x, a2);
                a3 = fma2(wH[7], h67.y, a3);
                red[r * 33 + lane] = hsum2(add2(add2(a0, a1), add2(a2, a3)));
            }
        }
        POLL(2u * i + 2u);
        __syncthreads();   // S4

        // ---- D: finalize h1_{i-1}; E: stage h0_i (LDGs issued first, fly under D) ----
        const bool doE = (i < Ssz);
        if (doE) {
            const float* src = g_h0[i & 1] + (size_t)(b0 + srow) * Hsz;
            e0 = __ldcg((const float4*)(src + sc * 4));
            e1 = __ldcg((const float4*)(src + (sc + 32) * 4));
        }
        if (i >= 1) {
            float s = bias1;
#pragma unroll
            for (int q = 0; q < 16; ++q) s += sRedB[q * 528 + warp * 33 + lane];
#pragma unroll
            for (int q = 0; q < 16; ++q) s += sRedA[q * 528 + warp * 33 + lane];
            __stcg(&g_h1[(i - 1) & 1][(size_t)(b0 + warp) * Hsz + h0c + lane], tanh_fast(s));
        }
        if (doE) {
            float* dst = sH0 + srow * WPAD;
            *(float4*)(dst + sc * 4)        = e0;
            *(float4*)(dst + (sc + 32) * 4) = e1;
            if (i + 1 < Ssz)
                p = g_pre0p[((size_t)cta * Ssz + i + 1) * 512 + warp * 32 + lane];
        }
        __syncthreads();   // S5
        if (tid == 0) st_release(&g_flags[cta], 2u * i + 3u);   // publish h1_{i-1}
    }

    // ================= phase 3: head (16 CTAs, one per batch group) =================
    if ((cta & 7) == 0) {
        POLL(2u * Ssz + 3u);
        __syncthreads();
        if (warp < 8) {
            const float bo = bout[0];
#pragma unroll
            for (int rr = 0; rr < 2; ++rr) {
                const int b = b0 + warp * 2 + rr;
                const float* h = g_h1[(Ssz - 1) & 1] + (size_t)b * Hsz;
                float s = 0.0f;
#pragma unroll
                for (int j = 0; j < 8; ++j)
                    s += __ldcg(&h[lane + 32 * j]) * Wout[lane + 32 * j];
#pragma unroll
                for (int o = 16; o > 0; o >>= 1) s += __shfl_down_sync(0xFFFFFFFFu, s, o);
                if (lane == 0) out[b] = 1.0f / (1.0f + expf(-(s + bo)));
            }
        }
    }
#undef POLL
}

// ---------------- launch ----------------
extern "C" void kernel_launch(void* const* d_in, const int* in_sizes, int n_in,
                              void* d_out, int out_size) {
    const float* x    = (const float*)d_in[0];
    const float* Wih0 = (const float*)d_in[1];
    const float* Whh0 = (const float*)d_in[2];
    const float* bih0 = (const float*)d_in[3];
    const float* bhh0 = (const float*)d_in[4];
    const float* Wih1 = (const float*)d_in[5];
    const float* Whh1 = (const float*)d_in[6];
    const float* bih1 = (const float*)d_in[7];
    const float* bhh1 = (const float*)d_in[8];
    const float* Wout = (const float*)d_in[9];
    const float* bout = (const float*)d_in[10];
    float* out = (float*)d_out;

    // smem: 2*16*WPAD + 32*528 floats = 8320 + 16896 = 25216 floats = 100,864 B
    const int smem_bytes = (2 * 16 * WPAD + 32 * 528) * (int)sizeof(float);
    static int configured = 0;
    if (!configured) {
        cudaFuncSetAttribute(fused_kernel, cudaFuncAttributeMaxDynamicSharedMemorySize, smem_bytes);
        configured = 1;
    }

    init_kernel<<<(Bsz * Hsz + 511) / 512, 512>>>();
    fused_kernel<<<NCTA, NTHR, smem_bytes>>>(x, Wih0, Whh0, bih0, bhh0,
                                             Wih1, Whh1, bih1, bhh1,
                                             Wout, bout, out);
}

// round 14
// speedup vs baseline: 1.4550x; 1.0678x over previous
#include <cuda_runtime.h>
#include <math.h>
#include <stdint.h>

#define Bsz 256
#define Ssz 2048
#define Dsz 64
#define Hsz 256
#define NCTA 128          // persistent CTAs, 1/SM, all co-resident
#define NTHR 512          // 16 warps; warp w owns k-slice [16w,16w+16) and row w
#define WPAD 260          // state row stride (floats)

// ---------------- device scratch ----------------
__device__ float g_pre0p[(size_t)NCTA * Ssz * 512];  // private pre0 [cta][s][row16][lane32]
__device__ float g_h0[2][Bsz * Hsz];                 // layer-0 state, double buffered
__device__ float g_h1[2][Bsz * Hsz];                 // layer-1 state, double buffered
__device__ unsigned int g_flags[NCTA];               // barrier flags (zeroed by init)

__device__ __forceinline__ float tanh_fast(float x) {
    float y; asm("tanh.approx.f32 %0, %1;" : "=f"(y) : "f"(x)); return y;
}
__device__ __forceinline__ unsigned long long fma2(unsigned long long a,
                                                   unsigned long long b,
                                                   unsigned long long c) {
    unsigned long long d;
    asm("fma.rn.f32x2 %0, %1, %2, %3;" : "=l"(d) : "l"(a), "l"(b), "l"(c));
    return d;
}
__device__ __forceinline__ unsigned long long add2(unsigned long long a,
                                                   unsigned long long b) {
    unsigned long long d;
    asm("add.rn.f32x2 %0, %1, %2;" : "=l"(d) : "l"(a), "l"(b));
    return d;
}
__device__ __forceinline__ float hsum2(unsigned long long a) {
    float2 f = *reinterpret_cast<float2*>(&a);
    return f.x + f.y;
}
__device__ __forceinline__ void st_release(unsigned int* p, unsigned int v) {
    asm volatile("st.release.gpu.global.u32 [%0], %1;" :: "l"(p), "r"(v) : "memory");
}
__device__ __forceinline__ unsigned int ld_acquire(const unsigned int* p) {
    unsigned int v;
    asm volatile("ld.acquire.gpu.global.u32 %0, [%1];" : "=r"(v) : "l"(p) : "memory");
    return v;
}

// ---------------- init: zero flags + seed states ----------------
__global__ void init_kernel() {
    const int idx = blockIdx.x * blockDim.x + threadIdx.x;
    if (idx < NCTA) g_flags[idx] = 0u;
    if (idx < Bsz * Hsz) {
        g_h1[0][idx] = 0.0f;
        g_h1[1][idx] = 0.0f;
    }
}

__global__ void __launch_bounds__(NTHR, 1)
fused_kernel(const float* __restrict__ x,
             const float* __restrict__ Wih0,
             const float* __restrict__ Whh0,
             const float* __restrict__ bih0,
             const float* __restrict__ bhh0,
             const float* __restrict__ Wih1,
             const float* __restrict__ Whh1,
             const float* __restrict__ bih1,
             const float* __restrict__ bhh1,
             const float* __restrict__ Wout,
             const float* __restrict__ bout,
             float* __restrict__ out) {
    extern __shared__ float smem[];
    float* sH0   = smem;                     // [16][WPAD]  h0_{i-1}
    float* sH1   = sH0 + 16 * WPAD;          // [16][WPAD]  h1_{i-2}
    float* sRedA = sH1 + 16 * WPAD;          // 16 tiles [16][33]: Whh0 partials, then Whh1
    float* sRedB = sRedA + 16 * 528;         // 16 tiles [16][33]: Wih1 partials

    const int tid  = threadIdx.x;
    const int cta  = blockIdx.x;
    const int grp8 = (cta >> 3) * 8;
    const int b0   = (cta >> 3) * 16;         // 16 batch rows
    const int h0c  = (cta & 7) * 32;          // 32 h columns
    const int lane = tid & 31;
    const int warp = tid >> 5;                // 0..15: k-slice AND finalize row

    const int srow = warp, sc = lane;         // staging: warp w stages row w

    // ================= phase 1: pre0_priv = x @ Wih0^T + (b_ih0+b_hh0) =================
    {
        float* sW = sH0;   // scratch, re-zeroed later
        for (int it = tid; it < 32 * 16; it += NTHR) {
            const int col = it >> 4, kq = it & 15;
            *(float4*)(sW + (kq * 32 + col) * 4) =
                *(const float4*)(Wih0 + (size_t)(h0c + col) * Dsz + kq * 4);
        }
        __syncthreads();
        const float bsum = bih0[h0c + lane] + bhh0[h0c + lane];

        for (int s = warp; s < Ssz; s += 16) {
            float* dst = g_pre0p + ((size_t)cta * Ssz + s) * 512;
#pragma unroll 2
            for (int r = 0; r < 16; ++r) {
                const float4* xr = (const float4*)(x + ((size_t)(b0 + r) * Ssz + s) * Dsz);
                float a = 0.0f;
#pragma unroll
                for (int c2 = 0; c2 < 2; ++c2) {
                    float4 xv[8];
#pragma unroll
                    for (int q = 0; q < 8; ++q) xv[q] = __ldg(xr + c2 * 8 + q);
#pragma unroll
                    for (int q = 0; q < 8; ++q) {
                        float4 w = *(const float4*)(sW + ((c2 * 8 + q) * 32 + lane) * 4);
                        a += w.x * xv[q].x + w.y * xv[q].y + w.z * xv[q].z + w.w * xv[q].w;
                    }
                }
                dst[r * 32 + lane] = a + bsum;
            }
        }
    }

    // ---- per-lane register weights: col = h0c+lane, k-slice [warp*16, +16) ----
    unsigned long long wA[8], wI[8], wH[8];
    {
        const size_t off = (size_t)(h0c + lane) * Hsz + warp * 16;
#pragma unroll
        for (int j = 0; j < 4; ++j) {
            ulonglong2 a = *(const ulonglong2*)(Whh0 + off + j * 4);
            ulonglong2 b = *(const ulonglong2*)(Wih1 + off + j * 4);
            ulonglong2 c = *(const ulonglong2*)(Whh1 + off + j * 4);
            wA[j * 2] = a.x; wA[j * 2 + 1] = a.y;
            wI[j * 2] = b.x; wI[j * 2 + 1] = b.y;
            wH[j * 2] = c.x; wH[j * 2 + 1] = c.y;
        }
    }
    const float bias1 = bih1[h0c + lane] + bhh1[h0c + lane];

    // ---- zero sH0 (= h0_{-1}); publish readiness (flag = 1) ----
    __syncthreads();   // pre0's sW use done
    for (int it = tid; it < 16 * WPAD; it += NTHR) sH0[it] = 0.0f;
    __syncthreads();
    if (tid == 0) st_release(&g_flags[cta], 1u);

#define POLL(VAL) do {                                                     \
        if (tid < 8) {                                                     \
            const unsigned int tgt = (VAL);                                \
            while (ld_acquire(&g_flags[grp8 + tid]) < tgt) { }             \
        }                                                                  \
    } while (0)

    float p = g_pre0p[(size_t)cta * Ssz * 512 + warp * 32 + lane];   // pre0 for i=0

    // ================= phase 2: pipelined two-layer recurrence =================
    for (int i = 0; i <= Ssz; ++i) {
        const bool doA  = (i < Ssz);   // h0_i work exists
        const bool doC  = (i >= 1);    // h1_{i-1} work exists

        // ---- A (merged): Whh0 partials AND Wih1 partials from ONE pass over sH0 ----
        {
            float* redA_ = sRedA + warp * 528;
            float* redB_ = sRedB + warp * 528;
            const float* S = sH0 + warp * 16;
#pragma unroll 2
            for (int r = 0; r < 16; ++r) {
                const ulonglong2* hp = (const ulonglong2*)(S + r * WPAD);
                ulonglong2 h01 = hp[0], h23 = hp[1], h45 = hp[2], h67 = hp[3];
                if (doA) {
                    unsigned long long a0 = fma2(wA[0], h01.x, 0ull);
                    unsigned long long a1 = fma2(wA[1], h01.y, 0ull);
                    unsigned long long a2 = fma2(wA[2], h23.x, 0ull);
                    unsigned long long a3 = fma2(wA[3], h23.y, 0ull);
                    a0 = fma2(wA[4], h45.x, a0);
                    a1 = fma2(wA[5], h45.y, a1);
                    a2 = fma2(wA[6], h67.x, a2);
                    a3 = fma2(wA[7], h67.y, a3);
                    redA_[r * 33 + lane] = hsum2(add2(add2(a0, a1), add2(a2, a3)));
                }
                if (doC) {
                    unsigned long long a0 = fma2(wI[0], h01.x, 0ull);
                    unsigned long long a1 = fma2(wI[1], h01.y, 0ull);
                    unsigned long long a2 = fma2(wI[2], h23.x, 0ull);
                    unsigned long long a3 = fma2(wI[3], h23.y, 0ull);
                    a0 = fma2(wI[4], h45.x, a0);
                    a1 = fma2(wI[5], h45.y, a1);
                    a2 = fma2(wI[6], h67.x, a2);
                    a3 = fma2(wI[7], h67.y, a3);
                    redB_[r * 33 + lane] = hsum2(add2(add2(a0, a1), add2(a2, a3)));
                }
            }
        }
        POLL(2u * i + 1u);   // peers' h1_{i-2} (published 1 iter ago: max slack)
        __syncthreads();     // S1

        // ---- B: stage h1_{i-2} (LDGs fly under h0 finalize) ----
        float4 e0, e1;
        {
            const float* src = g_h1[i & 1] + (size_t)(b0 + srow) * Hsz;  // (i-2)&1 == i&1
            e0 = __ldcg((const float4*)(src + sc * 4));
            e1 = __ldcg((const float4*)(src + (sc + 32) * 4));
        }
        if (doA) {           // finalize h0_i (warp w -> row w)
            float s = p;
#pragma unroll
            for (int q = 0; q < 16; ++q) s += sRedA[q * 528 + warp * 33 + lane];
            __stcg(&g_h0[i & 1][(size_t)(b0 + warp) * Hsz + h0c + lane], tanh_fast(s));
        }
        {
            float* dst = sH1 + srow * WPAD;
            *(float4*)(dst + sc * 4)        = e0;
            *(float4*)(dst + (sc + 32) * 4) = e1;
        }
        __syncthreads();     // S2
        if (tid == 0) st_release(&g_flags[cta], 2u * i + 2u);   // publish h0_i

        // ---- C2: Whh1 partials on sH1 (redA reused); poll peers' h0_i ----
        if (doC) {
            float* red = sRedA + warp * 528;
            const float* S = sH1 + warp * 16;
#pragma unroll 4
            for (int r = 0; r < 16; ++r) {
                const ulonglong2* hp = (const ulonglong2*)(S + r * WPAD);
                ulonglong2 h01 = hp[0], h23 = hp[1], h45 = hp[2], h67 = hp[3];
                unsigned long long a0 = fma2(wH[0], h01.x, 0ull);
                unsigned long long a1 = fma2(wH[1], h01.y, 0ull);
                unsigned long long a2 = fma2(wH[2], h23.x, 0ull);
                unsigned long long a3 = fma2(wH[3], h23.y, 0ull);
                a0 = fma2(wH[4], h45.x, a0);
                a1 = fma2(wH[5], h45.y, a1);
                a2 = fma2(wH[6], h67.x, a2);
                a3 = fma2(wH[7], h67.y, a3);
                red[r * 33 + lane] = hsum2(add2(add2(a0, a1), add2(a2, a3)));
            }
        }
        if (doA) POLL(2u * i + 2u);
        __syncthreads();     // S3

        // ---- D: finalize h1_{i-1}; stage h0_i (LDGs fly under finalize) ----
        if (doA) {
            const float* src = g_h0[i & 1] + (size_t)(b0 + srow) * Hsz;
            e0 = __ldcg((const float4*)(src + sc * 4));
            e1 = __ldcg((const float4*)(src + (sc + 32) * 4));
        }
        if (doC) {
            float s = bias1;
#pragma unroll
            for (int q = 0; q < 16; ++q) s += sRedB[q * 528 + warp * 33 + lane];
#pragma unroll
            for (int q = 0; q < 16; ++q) s += sRedA[q * 528 + warp * 33 + lane];
            __stcg(&g_h1[(i - 1) & 1][(size_t)(b0 + warp) * Hsz + h0c + lane], tanh_fast(s));
        }
        if (doA) {
            float* dst = sH0 + srow * WPAD;
            *(float4*)(dst + sc * 4)        = e0;
            *(float4*)(dst + (sc + 32) * 4) = e1;
            if (i + 1 < Ssz)
                p = g_pre0p[((size_t)cta * Ssz + i + 1) * 512 + warp * 32 + lane];
        }
        __syncthreads();     // S4
        if (tid == 0) st_release(&g_flags[cta], 2u * i + 3u);   // publish h1_{i-1}
    }

    // ================= phase 3: head (16 CTAs, one per batch group) =================
    if ((cta & 7) == 0) {
        POLL(2u * Ssz + 3u);
        __syncthreads();
        if (warp < 8) {
            const float bo = bout[0];
#pragma unroll
            for (int rr = 0; rr < 2; ++rr) {
                const int b = b0 + warp * 2 + rr;
                const float* h = g_h1[(Ssz - 1) & 1] + (size_t)b * Hsz;
                float s = 0.0f;
#pragma unroll
                for (int j = 0; j < 8; ++j)
                    s += __ldcg(&h[lane + 32 * j]) * Wout[lane + 32 * j];
#pragma unroll
                for (int o = 16; o > 0; o >>= 1) s += __shfl_down_sync(0xFFFFFFFFu, s, o);
                if (lane == 0) out[b] = 1.0f / (1.0f + expf(-(s + bo)));
            }
        }
    }
#undef POLL
}

// ---------------- launch ----------------
extern "C" void kernel_launch(void* const* d_in, const int* in_sizes, int n_in,
                              void* d_out, int out_size) {
    const float* x    = (const float*)d_in[0];
    const float* Wih0 = (const float*)d_in[1];
    const float* Whh0 = (const float*)d_in[2];
    const float* bih0 = (const float*)d_in[3];
    const float* bhh0 = (const float*)d_in[4];
    const float* Wih1 = (const float*)d_in[5];
    const float* Whh1 = (const float*)d_in[6];
    const float* bih1 = (const float*)d_in[7];
    const float* bhh1 = (const float*)d_in[8];
    const float* Wout = (const float*)d_in[9];
    const float* bout = (const float*)d_in[10];
    float* out = (float*)d_out;

    // smem: 2*16*WPAD + 32*528 floats = 25216 floats = 100,864 B
    const int smem_bytes = (2 * 16 * WPAD + 32 * 528) * (int)sizeof(float);
    static int configured = 0;
    if (!configured) {
        cudaFuncSetAttribute(fused_kernel, cudaFuncAttributeMaxDynamicSharedMemorySize, smem_bytes);
        configured = 1;
    }

    init_kernel<<<(Bsz * Hsz + 511) / 512, 512>>>();
    fused_kernel<<<NCTA, NTHR, smem_bytes>>>(x, Wih0, Whh0, bih0, bhh0,
                                             Wih1, Whh1, bih1, bhh1,
                                             Wout, bout, out);
}

// round 15
// speedup vs baseline: 1.5597x; 1.0719x over previous
#include <cuda_runtime.h>
#include <math.h>
#include <stdint.h>

#define Bsz 256
#define Ssz 2048
#define Dsz 64
#define Hsz 256
#define NCTA 128          // persistent CTAs, 1/SM, all co-resident
#define NTHR 512          // 16 warps; warp w owns k-slice [16w,16w+16) and row w
#define WPAD 260          // state row stride (floats)

// ---------------- device scratch ----------------
__device__ float g_pre0p[(size_t)NCTA * Ssz * 512];  // private pre0 [cta][s][row16][lane32]
__device__ float g_h0[2][Bsz * Hsz];                 // layer-0 state, double buffered
__device__ float g_h1[2][Bsz * Hsz];                 // layer-1 state, double buffered
__device__ unsigned int g_flags[NCTA];               // barrier flags (zeroed by init)

__device__ __forceinline__ float tanh_fast(float x) {
    float y; asm("tanh.approx.f32 %0, %1;" : "=f"(y) : "f"(x)); return y;
}
__device__ __forceinline__ unsigned long long fma2(unsigned long long a,
                                                   unsigned long long b,
                                                   unsigned long long c) {
    unsigned long long d;
    asm("fma.rn.f32x2 %0, %1, %2, %3;" : "=l"(d) : "l"(a), "l"(b), "l"(c));
    return d;
}
__device__ __forceinline__ unsigned long long add2(unsigned long long a,
                                                   unsigned long long b) {
    unsigned long long d;
    asm("add.rn.f32x2 %0, %1, %2;" : "=l"(d) : "l"(a), "l"(b));
    return d;
}
__device__ __forceinline__ float hsum2(unsigned long long a) {
    float2 f = *reinterpret_cast<float2*>(&a);
    return f.x + f.y;
}
__device__ __forceinline__ unsigned long long pack2(float lo, float hi) {
    unsigned long long d;
    asm("mov.b64 %0, {%1, %2};" : "=l"(d) : "f"(lo), "f"(hi));
    return d;
}
__device__ __forceinline__ void st_release(unsigned int* p, unsigned int v) {
    asm volatile("st.release.gpu.global.u32 [%0], %1;" :: "l"(p), "r"(v) : "memory");
}
__device__ __forceinline__ unsigned int ld_acquire(const unsigned int* p) {
    unsigned int v;
    asm volatile("ld.acquire.gpu.global.u32 %0, [%1];" : "=r"(v) : "l"(p) : "memory");
    return v;
}

// ---------------- init: zero flags + seed states ----------------
__global__ void init_kernel() {
    const int idx = blockIdx.x * blockDim.x + threadIdx.x;
    if (idx < NCTA) g_flags[idx] = 0u;
    if (idx < Bsz * Hsz) {
        g_h1[0][idx] = 0.0f;
        g_h1[1][idx] = 0.0f;
    }
}

__global__ void __launch_bounds__(NTHR, 1)
fused_kernel(const float* __restrict__ x,
             const float* __restrict__ Wih0,
             const float* __restrict__ Whh0,
             const float* __restrict__ bih0,
             const float* __restrict__ bhh0,
             const float* __restrict__ Wih1,
             const float* __restrict__ Whh1,
             const float* __restrict__ bih1,
             const float* __restrict__ bhh1,
             const float* __restrict__ Wout,
             const float* __restrict__ bout,
             float* __restrict__ out) {
    extern __shared__ float smem[];
    float* sH0   = smem;                     // [16][WPAD]  h0_{i-1}
    float* sH1   = sH0 + 16 * WPAD;          // [16][WPAD]  h1_{i-2}
    float* sRedA = sH1 + 16 * WPAD;          // 16 tiles [16][33]: Whh0 partials, then Whh1
    float* sRedB = sRedA + 16 * 528;         // 16 tiles [16][33]: Wih1 partials
    float* sWH   = sRedB + 16 * 528;         // [256][32]  Whh1 weights, k-major

    const int tid  = threadIdx.x;
    const int cta  = blockIdx.x;
    const int grp8 = (cta >> 3) * 8;
    const int b0   = (cta >> 3) * 16;         // 16 batch rows
    const int h0c  = (cta & 7) * 32;          // 32 h columns
    const int lane = tid & 31;
    const int warp = tid >> 5;                // 0..15: k-slice AND finalize row

    const int srow = warp, sc = lane;         // staging: warp w stages row w

    // ================= phase 1: pre0_priv = x @ Wih0^T + (b_ih0+b_hh0) =================
    {
        float* sW = sH0;   // scratch, re-zeroed later
        for (int it = tid; it < 32 * 16; it += NTHR) {
            const int col = it >> 4, kq = it & 15;
            *(float4*)(sW + (kq * 32 + col) * 4) =
                *(const float4*)(Wih0 + (size_t)(h0c + col) * Dsz + kq * 4);
        }
        __syncthreads();
        const float bsum = bih0[h0c + lane] + bhh0[h0c + lane];

        for (int s = warp; s < Ssz; s += 16) {
            float* dst = g_pre0p + ((size_t)cta * Ssz + s) * 512;
#pragma unroll 2
            for (int r = 0; r < 16; ++r) {
                const float4* xr = (const float4*)(x + ((size_t)(b0 + r) * Ssz + s) * Dsz);
                float a = 0.0f;
#pragma unroll
                for (int c2 = 0; c2 < 2; ++c2) {
                    float4 xv[8];
#pragma unroll
                    for (int q = 0; q < 8; ++q) xv[q] = __ldg(xr + c2 * 8 + q);
#pragma unroll
                    for (int q = 0; q < 8; ++q) {
                        float4 w = *(const float4*)(sW + ((c2 * 8 + q) * 32 + lane) * 4);
                        a += w.x * xv[q].x + w.y * xv[q].y + w.z * xv[q].z + w.w * xv[q].w;
                    }
                }
                dst[r * 32 + lane] = a + bsum;
            }
        }
    }

    // ---- persistent register weights (Whh0, Wih1); Whh1 goes to SMEM ----
    unsigned long long wA[8], wI[8];
    {
        const size_t off = (size_t)(h0c + lane) * Hsz + warp * 16;
#pragma unroll
        for (int j = 0; j < 4; ++j) {
            ulonglong2 a = *(const ulonglong2*)(Whh0 + off + j * 4);
            ulonglong2 b = *(const ulonglong2*)(Wih1 + off + j * 4);
            wA[j * 2] = a.x; wA[j * 2 + 1] = a.y;
            wI[j * 2] = b.x; wI[j * 2 + 1] = b.y;
        }
    }
    const float bias1 = bih1[h0c + lane] + bhh1[h0c + lane];

    __syncthreads();   // pre0's sW use done
    // ---- Whh1 -> sWH[k][col] (k-major; C2 reads one 128B row per k) ----
    {
        const size_t off = (size_t)(h0c + lane) * Hsz + warp * 16;
#pragma unroll
        for (int j = 0; j < 4; ++j) {
            ulonglong2 c = *(const ulonglong2*)(Whh1 + off + j * 4);
            float2 f0 = *reinterpret_cast<float2*>(&c.x);
            float2 f1 = *reinterpret_cast<float2*>(&c.y);
            sWH[(warp * 16 + j * 4 + 0) * 32 + lane] = f0.x;
            sWH[(warp * 16 + j * 4 + 1) * 32 + lane] = f0.y;
            sWH[(warp * 16 + j * 4 + 2) * 32 + lane] = f1.x;
            sWH[(warp * 16 + j * 4 + 3) * 32 + lane] = f1.y;
        }
    }
    // ---- zero sH0 (= h0_{-1}); publish readiness (flag = 1) ----
    for (int it = tid; it < 16 * WPAD; it += NTHR) sH0[it] = 0.0f;
    __syncthreads();
    if (tid == 0) st_release(&g_flags[cta], 1u);

#define POLL(VAL) do {                                                     \
        if (tid < 8) {                                                     \
            const unsigned int tgt = (VAL);                                \
            while (ld_acquire(&g_flags[grp8 + tid]) < tgt) { }             \
        }                                                                  \
    } while (0)

    float p = g_pre0p[(size_t)cta * Ssz * 512 + warp * 32 + lane];   // pre0 for i=0

    // ================= phase 2: pipelined two-layer recurrence =================
    for (int i = 0; i <= Ssz; ++i) {
        const bool doA = (i < Ssz);    // h0_i work exists
        const bool doC = (i >= 1);     // h1_{i-1} work exists

        // ---- A (merged): Whh0 AND Wih1 partials, one pass over sH0, row-prefetched ----
        {
            float* redA_ = sRedA + warp * 528;
            float* redB_ = sRedB + warp * 528;
            const float* S = sH0 + warp * 16;
            ulonglong2 c0 = ((const ulonglong2*)S)[0];
            ulonglong2 c1 = ((const ulonglong2*)S)[1];
            ulonglong2 c2 = ((const ulonglong2*)S)[2];
            ulonglong2 c3 = ((const ulonglong2*)S)[3];
#pragma unroll
            for (int r = 0; r < 16; ++r) {
                ulonglong2 n0 = c0, n1 = c1, n2 = c2, n3 = c3;
                if (r < 15) {
                    const ulonglong2* Sn = (const ulonglong2*)(S + (r + 1) * WPAD);
                    n0 = Sn[0]; n1 = Sn[1]; n2 = Sn[2]; n3 = Sn[3];
                }
                if (doA) {
                    unsigned long long a0 = fma2(wA[0], c0.x, 0ull);
                    unsigned long long a1 = fma2(wA[1], c0.y, 0ull);
                    unsigned long long a2 = fma2(wA[2], c1.x, 0ull);
                    unsigned long long a3 = fma2(wA[3], c1.y, 0ull);
                    a0 = fma2(wA[4], c2.x, a0);
                    a1 = fma2(wA[5], c2.y, a1);
                    a2 = fma2(wA[6], c3.x, a2);
                    a3 = fma2(wA[7], c3.y, a3);
                    redA_[r * 33 + lane] = hsum2(add2(add2(a0, a1), add2(a2, a3)));
                }
                if (doC) {
                    unsigned long long a0 = fma2(wI[0], c0.x, 0ull);
                    unsigned long long a1 = fma2(wI[1], c0.y, 0ull);
                    unsigned long long a2 = fma2(wI[2], c1.x, 0ull);
                    unsigned long long a3 = fma2(wI[3], c1.y, 0ull);
                    a0 = fma2(wI[4], c2.x, a0);
                    a1 = fma2(wI[5], c2.y, a1);
                    a2 = fma2(wI[6], c3.x, a2);
                    a3 = fma2(wI[7], c3.y, a3);
                    redB_[r * 33 + lane] = hsum2(add2(add2(a0, a1), add2(a2, a3)));
                }
                c0 = n0; c1 = n1; c2 = n2; c3 = n3;
            }
        }
        POLL(2u * i + 1u);   // peers' h1_{i-2} (published 1 iter ago: max slack)
        __syncthreads();     // S1

        // ---- B: stage h1_{i-2} (LDGs fly under h0 finalize) ----
        float4 e0, e1;
        {
            const float* src = g_h1[i & 1] + (size_t)(b0 + srow) * Hsz;  // (i-2)&1 == i&1
            e0 = __ldcg((const float4*)(src + sc * 4));
            e1 = __ldcg((const float4*)(src + (sc + 32) * 4));
        }
        if (doA) {           // finalize h0_i (warp w -> row w), tree reduce
            float t[16];
#pragma unroll
            for (int q = 0; q < 16; ++q) t[q] = sRedA[q * 528 + warp * 33 + lane];
#pragma unroll
            for (int st = 1; st < 16; st <<= 1)
#pragma unroll
                for (int j = 0; j < 16; j += 2 * st) t[j] += t[j + st];
            __stcg(&g_h0[i & 1][(size_t)(b0 + warp) * Hsz + h0c + lane],
                   tanh_fast(p + t[0]));
        }
        {
            float* dst = sH1 + srow * WPAD;
            *(float4*)(dst + sc * 4)        = e0;
            *(float4*)(dst + (sc + 32) * 4) = e1;
        }
        __syncthreads();     // S2
        if (tid == 0) st_release(&g_flags[cta], 2u * i + 2u);   // publish h0_i

        // ---- C2: Whh1 partials on sH1 (weights from sWH, row-prefetched) ----
        if (doC) {
            unsigned long long wH[8];
#pragma unroll
            for (int j = 0; j < 8; ++j) {
                const float lo = sWH[(warp * 16 + 2 * j + 0) * 32 + lane];
                const float hi = sWH[(warp * 16 + 2 * j + 1) * 32 + lane];
                wH[j] = pack2(lo, hi);
            }
            float* red = sRedA + warp * 528;     // A tiles consumed at B: reuse
            const float* S = sH1 + warp * 16;
            ulonglong2 c0 = ((const ulonglong2*)S)[0];
            ulonglong2 c1 = ((const ulonglong2*)S)[1];
            ulonglong2 c2 = ((const ulonglong2*)S)[2];
            ulonglong2 c3 = ((const ulonglong2*)S)[3];
#pragma unroll
            for (int r = 0; r < 16; ++r) {
                ulonglong2 n0 = c0, n1 = c1, n2 = c2, n3 = c3;
                if (r < 15) {
                    const ulonglong2* Sn = (const ulonglong2*)(S + (r + 1) * WPAD);
                    n0 = Sn[0]; n1 = Sn[1]; n2 = Sn[2]; n3 = Sn[3];
                }
                unsigned long long a0 = fma2(wH[0], c0.x, 0ull);
                unsigned long long a1 = fma2(wH[1], c0.y, 0ull);
                unsigned long long a2 = fma2(wH[2], c1.x, 0ull);
                unsigned long long a3 = fma2(wH[3], c1.y, 0ull);
                a0 = fma2(wH[4], c2.x, a0);
                a1 = fma2(wH[5], c2.y, a1);
                a2 = fma2(wH[6], c3.x, a2);
                a3 = fma2(wH[7], c3.y, a3);
                red[r * 33 + lane] = hsum2(add2(add2(a0, a1), add2(a2, a3)));
                c0 = n0; c1 = n1; c2 = n2; c3 = n3;
            }
        }
        if (doA) POLL(2u * i + 2u);
        __syncthreads();     // S3

        // ---- D: finalize h1_{i-1} (tree reduce); stage h0_i (LDGs fly under it) ----
        if (doA) {
            const float* src = g_h0[i & 1] + (size_t)(b0 + srow) * Hsz;
            e0 = __ldcg((const float4*)(src + sc * 4));
            e1 = __ldcg((const float4*)(src + (sc + 32) * 4));
        }
        if (doC) {
            float t[16], u[16];
#pragma unroll
            for (int q = 0; q < 16; ++q) t[q] = sRedB[q * 528 + warp * 33 + lane];
#pragma unroll
            for (int q = 0; q < 16; ++q) u[q] = sRedA[q * 528 + warp * 33 + lane];
#pragma unroll
            for (int st = 1; st < 16; st <<= 1)
#pragma unroll
                for (int j = 0; j < 16; j += 2 * st) { t[j] += t[j + st]; u[j] += u[j + st]; }
            __stcg(&g_h1[(i - 1) & 1][(size_t)(b0 + warp) * Hsz + h0c + lane],
                   tanh_fast(bias1 + t[0] + u[0]));
        }
        if (doA) {
            float* dst = sH0 + srow * WPAD;
            *(float4*)(dst + sc * 4)        = e0;
            *(float4*)(dst + (sc + 32) * 4) = e1;
            if (i + 1 < Ssz)
                p = g_pre0p[((size_t)cta * Ssz + i + 1) * 512 + warp * 32 + lane];
        }
        __syncthreads();     // S4
        if (tid == 0) st_release(&g_flags[cta], 2u * i + 3u);   // publish h1_{i-1}
    }

    // ================= phase 3: head (16 CTAs, one per batch group) =================
    if ((cta & 7) == 0) {
        POLL(2u * Ssz + 3u);
        __syncthreads();
        if (warp < 8) {
            const float bo = bout[0];
#pragma unroll
            for (int rr = 0; rr < 2; ++rr) {
                const int b = b0 + warp * 2 + rr;
                const float* h = g_h1[(Ssz - 1) & 1] + (size_t)b * Hsz;
                float s = 0.0f;
#pragma unroll
                for (int j = 0; j < 8; ++j)
                    s += __ldcg(&h[lane + 32 * j]) * Wout[lane + 32 * j];
#pragma unroll
                for (int o = 16; o > 0; o >>= 1) s += __shfl_down_sync(0xFFFFFFFFu, s, o);
                if (lane == 0) out[b] = 1.0f / (1.0f + expf(-(s + bo)));
            }
        }
    }
#undef POLL
}

// ---------------- launch ----------------
extern "C" void kernel_launch(void* const* d_in, const int* in_sizes, int n_in,
                              void* d_out, int out_size) {
    const float* x    = (const float*)d_in[0];
    const float* Wih0 = (const float*)d_in[1];
    const float* Whh0 = (const float*)d_in[2];
    const float* bih0 = (const float*)d_in[3];
    const float* bhh0 = (const float*)d_in[4];
    const float* Wih1 = (const float*)d_in[5];
    const float* Whh1 = (const float*)d_in[6];
    const float* bih1 = (const float*)d_in[7];
    const float* bhh1 = (const float*)d_in[8];
    const float* Wout = (const float*)d_in[9];
    const float* bout = (const float*)d_in[10];
    float* out = (float*)d_out;

    // smem: 2*16*WPAD + 32*528 + 256*32 floats = 33408 floats = 133,632 B
    const int smem_bytes = (2 * 16 * WPAD + 32 * 528 + 256 * 32) * (int)sizeof(float);
    static int configured = 0;
    if (!configured) {
        cudaFuncSetAttribute(fused_kernel, cudaFuncAttributeMaxDynamicSharedMemorySize, smem_bytes);
        configured = 1;
    }

    init_kernel<<<(Bsz * Hsz + 511) / 512, 512>>>();
    fused_kernel<<<NCTA, NTHR, smem_bytes>>>(x, Wih0, Whh0, bih0, bhh0,
                                             Wih1, Whh1, bih1, bhh1,
                                             Wout, bout, out);
}